// round 15
// baseline (speedup 1.0000x reference)
#include <cuda_runtime.h>
#include <cuda_bf16.h>
#include <math.h>
#include <cstdint>

#define BATCH  16
#define CCH    512
#define LSP    1024
#define NHEADS 8

typedef __nv_bfloat16 bf16;
typedef __nv_bfloat162 bf162;

// ---------------- scratch (static device globals; no allocs) ----------------
__device__ bf16 g_xn[BATCH * CCH * LSP];
__device__ bf16 g_cn[BATCH * CCH * LSP];
__device__ bf16 g_q [BATCH * CCH * LSP];
__device__ bf16 g_kv[BATCH * 2 * CCH * LSP];
__device__ bf16 g_o [BATCH * CCH * LSP];
__device__ bf16 g_wq [CCH * CCH];
__device__ bf16 g_wkv[2 * CCH * CCH];
__device__ bf16 g_wp [CCH * CCH];

// ---------------- PTX helpers ----------------
__device__ __forceinline__ unsigned int smem_u32(const void* p) {
    return (unsigned int)__cvta_generic_to_shared(p);
}
#define CP_ASYNC16(dst, src) \
    asm volatile("cp.async.cg.shared.global [%0], [%1], 16;\n" :: "r"(dst), "l"(src))
#define CP_COMMIT() asm volatile("cp.async.commit_group;\n" ::)
#define CP_WAIT1()  asm volatile("cp.async.wait_group 1;\n" ::)
#define CP_WAIT0()  asm volatile("cp.async.wait_group 0;\n" ::)
#define LDSM4(r0,r1,r2,r3,addr) \
    asm volatile("ldmatrix.sync.aligned.m8n8.x4.shared.b16 {%0,%1,%2,%3},[%4];" \
        : "=r"(r0),"=r"(r1),"=r"(r2),"=r"(r3) : "r"(addr))
#define LDSM4T(r0,r1,r2,r3,addr) \
    asm volatile("ldmatrix.sync.aligned.m8n8.x4.trans.shared.b16 {%0,%1,%2,%3},[%4];" \
        : "=r"(r0),"=r"(r1),"=r"(r2),"=r"(r3) : "r"(addr))
#define MMA16816(c,a,b0,b1) \
    asm volatile("mma.sync.aligned.m16n8k16.row.col.f32.bf16.bf16.f32 " \
        "{%0,%1,%2,%3},{%4,%5,%6,%7},{%8,%9},{%0,%1,%2,%3};" \
        : "+f"(c[0]),"+f"(c[1]),"+f"(c[2]),"+f"(c[3]) \
        : "r"(a[0]),"r"(a[1]),"r"(a[2]),"r"(a[3]),"r"(b0),"r"(b1))

__device__ __forceinline__ unsigned int packbf2(float a, float b) {
    bf162 t = __floats2bfloat162_rn(a, b);
    return *(unsigned int*)&t;
}

// ---------------- head kernel: reg-cached GroupNorm + weight cvt ------------
__global__ __launch_bounds__(256) void head_kernel(
    const float* __restrict__ x0, const float* __restrict__ w0,
    const float* __restrict__ b0, bf16* __restrict__ out0,
    const float* __restrict__ x1, const float* __restrict__ w1,
    const float* __restrict__ b1, bf16* __restrict__ out1,
    const float* __restrict__ cs0, bf16* cd0, int n0,
    const float* __restrict__ cs1, bf16* cd1, int n1,
    const float* __restrict__ cs2, bf16* cd2, int n2)
{
    int bg = blockIdx.x;
    int tid = threadIdx.x;

    if (bg >= 2 * BATCH * 32) {
        int i = (bg - 2 * BATCH * 32) * 256 + tid;
        const float* src; bf16* dst;
        if (i < n0)                { src = cs0; dst = cd0; }
        else if (i < n0 + n1)      { i -= n0; src = cs1; dst = cd1; }
        else if (i < n0 + n1 + n2) { i -= n0 + n1; src = cs2; dst = cd2; }
        else return;
        float4 v = ((const float4*)src)[i];
        ((bf162*)dst)[2 * i]     = __floats2bfloat162_rn(v.x, v.y);
        ((bf162*)dst)[2 * i + 1] = __floats2bfloat162_rn(v.z, v.w);
        return;
    }

    const float* x; const float* w; const float* bb; bf16* out;
    if (bg < BATCH * 32) { x = x0; w = w0; bb = b0; out = out0; }
    else { bg -= BATCH * 32; x = x1; w = w1; bb = b1; out = out1; }
    int g = bg & 31;
    const float4* x4 = (const float4*)(x + (size_t)bg * 16384);
    bf162*        o2 = (bf162*)(out + (size_t)bg * 16384);

    float4 v[16];
    #pragma unroll
    for (int t = 0; t < 16; t++) v[t] = x4[tid + t * 256];

    float s = 0.f, ss = 0.f;
    #pragma unroll
    for (int t = 0; t < 16; t++) {
        s  += v[t].x + v[t].y + v[t].z + v[t].w;
        ss += v[t].x*v[t].x + v[t].y*v[t].y + v[t].z*v[t].z + v[t].w*v[t].w;
    }
    __shared__ float rs[8], rss[8];
    #pragma unroll
    for (int o = 16; o; o >>= 1) {
        s  += __shfl_xor_sync(~0u, s, o);
        ss += __shfl_xor_sync(~0u, ss, o);
    }
    if ((tid & 31) == 0) { rs[tid >> 5] = s; rss[tid >> 5] = ss; }
    __syncthreads();
    if (tid < 32) {
        s  = (tid < 8) ? rs[tid]  : 0.f;
        ss = (tid < 8) ? rss[tid] : 0.f;
        #pragma unroll
        for (int o = 4; o; o >>= 1) {
            s  += __shfl_xor_sync(~0u, s, o);
            ss += __shfl_xor_sync(~0u, ss, o);
        }
        if (tid == 0) { rs[0] = s; rss[0] = ss; }
    }
    __syncthreads();
    float mean = rs[0] * (1.f / 16384.f);
    float var  = rss[0] * (1.f / 16384.f) - mean * mean;
    float inv  = rsqrtf(var + 1e-5f);

    #pragma unroll
    for (int t = 0; t < 16; t++) {
        int i = tid + t * 256;
        int c = g * 16 + (i >> 8);
        float sc = w[c] * inv;
        float sh = bb[c] - mean * sc;
        o2[2 * i]     = __floats2bfloat162_rn(v[t].x * sc + sh, v[t].y * sc + sh);
        o2[2 * i + 1] = __floats2bfloat162_rn(v[t].z * sc + sh, v[t].w * sc + sh);
    }
}

// ---------------- conv1x1 GEMM core (R11/R9 winner, unchanged) --------------
#define A_ST 16384
#define B_OFF (3 * A_ST)

template<bool BF16OUT>
__device__ __forceinline__ void gemm_body(const bf16* __restrict__ in,
                                          const bf16* __restrict__ W,
                                          const float* __restrict__ bias,
                                          const float* __restrict__ resid,
                                          void* __restrict__ outp, int O,
                                          int b, int o0, int l0, char* smraw)
{
    const unsigned int sbase = smem_u32(smraw);
    int tid = threadIdx.x, wid = tid >> 5, lane = tid & 31;
    int wm = wid >> 1, wn = wid & 1;
    int gid = lane >> 2, qtid = lane & 3;
    int lg = lane >> 3, lr = lane & 7;

    const bf16* Xb = in + (size_t)b * CCH * LSP;

    auto stage = [&](int s, int kc) {
        const bf16* Aw = W  + (size_t)o0 * CCH + kc * 64;
        const bf16* Bx = Xb + (size_t)(kc * 64) * LSP + l0;
        #pragma unroll
        for (int t = 0; t < 4; t++) {
            int idx = tid + t * 256;
            int ar = idx >> 3, g = idx & 7;
            unsigned int dst = sbase + s * A_ST + ar * 128 + ((g ^ (ar & 7)) << 4);
            CP_ASYNC16(dst, Aw + (size_t)ar * CCH + g * 8);
        }
        #pragma unroll
        for (int t = 0; t < 4; t++) {
            int idx = tid + t * 256;
            int br = idx >> 4, g = idx & 15;
            unsigned int dst = sbase + B_OFF + s * A_ST + br * 256 + ((g ^ (br & 7)) << 4);
            CP_ASYNC16(dst, Bx + (size_t)br * LSP + g * 8);
        }
        CP_COMMIT();
    };

    float acc[2][8][4] = {};

    const int T = CCH / 64;
    stage(0, 0);
    stage(1, 1);

    for (int i = 0; i < T; i++) {
        int s = i % 3;
        if (i == T - 1) { CP_WAIT0(); } else { CP_WAIT1(); }
        __syncthreads();
        if (i + 2 < T) stage((i + 2) % 3, i + 2);

        unsigned int abase = sbase + s * A_ST;
        unsigned int bbase = sbase + B_OFF + s * A_ST;
        #pragma unroll
        for (int ks = 0; ks < 4; ks++) {
            unsigned int af[2][4];
            #pragma unroll
            for (int mi = 0; mi < 2; mi++) {
                int mrow = wm * 32 + mi * 16 + (lg & 1) * 8 + lr;
                int kg   = (ks * 16 + (lg >> 1) * 8) >> 3;
                LDSM4(af[mi][0], af[mi][1], af[mi][2], af[mi][3],
                      abase + mrow * 128 + ((kg ^ (mrow & 7)) << 4));
            }
            #pragma unroll
            for (int np = 0; np < 4; np++) {
                int krow = ks * 16 + (lg & 1) * 8 + lr;
                int ng   = (wn * 64 + np * 16 + (lg >> 1) * 8) >> 3;
                unsigned int b0, b1, b2, b3;
                LDSM4T(b0, b1, b2, b3,
                       bbase + krow * 256 + ((ng ^ (krow & 7)) << 4));
                #pragma unroll
                for (int mi = 0; mi < 2; mi++) {
                    MMA16816(acc[mi][np * 2],     af[mi], b0, b1);
                    MMA16816(acc[mi][np * 2 + 1], af[mi], b2, b3);
                }
            }
        }
    }

    #pragma unroll
    for (int mi = 0; mi < 2; mi++) {
        int r0 = wm * 32 + mi * 16 + gid;
        float bi0 = bias[o0 + r0];
        float bi1 = bias[o0 + r0 + 8];
        size_t row0 = ((size_t)b * O + o0 + r0) * LSP + l0;
        size_t row1 = row0 + (size_t)8 * LSP;
        #pragma unroll
        for (int t = 0; t < 8; t++) {
            int c = wn * 64 + t * 8 + qtid * 2;
            if (BF16OUT) {
                bf16* ob = (bf16*)outp;
                *(unsigned int*)&ob[row0 + c] = packbf2(acc[mi][t][0] + bi0, acc[mi][t][1] + bi0);
                *(unsigned int*)&ob[row1 + c] = packbf2(acc[mi][t][2] + bi1, acc[mi][t][3] + bi1);
            } else {
                float* of = (float*)outp;
                float2 rv0 = *(const float2*)&resid[row0 + c];
                float2 rv1 = *(const float2*)&resid[row1 + c];
                float2 v0 = {acc[mi][t][0] + bi0 + rv0.x, acc[mi][t][1] + bi0 + rv0.y};
                float2 v1 = {acc[mi][t][2] + bi1 + rv1.x, acc[mi][t][3] + bi1 + rv1.y};
                *(float2*)&of[row0 + c] = v0;
                *(float2*)&of[row1 + c] = v1;
            }
        }
    }
}

// merged q + kv GEMM: y in [0,4) -> q from xn; y in [4,12) -> kv from cn
__global__ __launch_bounds__(256, 2) void gemm_qkv(const bf16* __restrict__ xn,
                                                   const bf16* __restrict__ cn,
                                                   const bf16* __restrict__ wq,
                                                   const bf16* __restrict__ wkv,
                                                   const float* __restrict__ qb,
                                                   const float* __restrict__ kvb,
                                                   bf16* __restrict__ qo,
                                                   bf16* __restrict__ kvo)
{
    extern __shared__ char smraw[];
    int y = blockIdx.y;
    if (y < 4)
        gemm_body<true>(xn, wq, qb, nullptr, qo, CCH,
                        blockIdx.z, y * 128, blockIdx.x * 128, smraw);
    else
        gemm_body<true>(cn, wkv, kvb, nullptr, kvo, 2 * CCH,
                        blockIdx.z, (y - 4) * 128, blockIdx.x * 128, smraw);
}

__global__ __launch_bounds__(256, 2) void gemm_proj(const bf16* __restrict__ in,
                                                    const bf16* __restrict__ W,
                                                    const float* __restrict__ bias,
                                                    const float* __restrict__ resid,
                                                    float* __restrict__ outp)
{
    extern __shared__ char smraw[];
    gemm_body<false>(in, W, bias, resid, outp, CCH,
                     blockIdx.z, blockIdx.y * 128, blockIdx.x * 128, smraw);
}

// ---------------- attention: 4 warps x 2 m-tiles (crossbar halved) ----------
// Block = 128 thr, 128 queries; each warp owns 32 queries (2 m16 tiles).
// K/V fragments loaded once per warp and reused for both m-tiles.
#define QI 136
#define KJ 72
#define Q_BYTES (64 * QI * 2)
#define KV_BYTES (64 * KJ * 2)
#define ATTN_SMEM (Q_BYTES + 4 * KV_BYTES)

__global__ __launch_bounds__(128, 2) void attn_mma(const bf16* __restrict__ qb,
                                                   const bf16* __restrict__ kvb,
                                                   bf16* __restrict__ ob)
{
    extern __shared__ char asmraw[];
    bf16* Qs = (bf16*)asmraw;
    const unsigned int sb = smem_u32(asmraw);
    const unsigned int kbuf0 = sb + Q_BYTES;
    const unsigned int vbuf0 = sb + Q_BYTES + 2 * KV_BYTES;

    int i0 = blockIdx.x * 128;
    int h  = blockIdx.y;
    int b  = blockIdx.z;
    int tid = threadIdx.x, wid = tid >> 5, lane = tid & 31;
    int gid = lane >> 2, qtid = lane & 3;
    int ibase = wid * 32;
    int lg = lane >> 3, lr = lane & 7;

    const bf16* qp = qb  + ((size_t)b * CCH     + h * 64) * LSP;
    const bf16* kp = kvb + ((size_t)b * 2 * CCH + h * 64) * LSP;
    const bf16* vp = kvb + ((size_t)b * 2 * CCH + CCH + h * 64) * LSP;
    bf16*       op = ob  + ((size_t)b * CCH     + h * 64) * LSP;

    int dk = tid >> 1, q4 = tid & 1;   // row dk (0..63), 32 bf16 at q4*32

    auto stageKV = [&](int s, int kt) {
        const bf16* ks_ = kp + (size_t)dk * LSP + kt * 64 + q4 * 32;
        const bf16* vs_ = vp + (size_t)dk * LSP + kt * 64 + q4 * 32;
        unsigned int ko = kbuf0 + s * KV_BYTES + dk * (KJ * 2) + q4 * 64;
        unsigned int vo = vbuf0 + s * KV_BYTES + dk * (KJ * 2) + q4 * 64;
        CP_ASYNC16(ko,      ks_);
        CP_ASYNC16(ko + 16, ks_ + 8);
        CP_ASYNC16(ko + 32, ks_ + 16);
        CP_ASYNC16(ko + 48, ks_ + 24);
        CP_ASYNC16(vo,      vs_);
        CP_ASYNC16(vo + 16, vs_ + 8);
        CP_ASYNC16(vo + 32, vs_ + 16);
        CP_ASYNC16(vo + 48, vs_ + 24);
        CP_COMMIT();
    };

    stageKV(0, 0);

    // load Q tile: 64 rows x 128 cols, thread d = tid>>1, 64 bf16 at (tid&1)*64
    {
        int d = tid >> 1, c = (tid & 1) * 64;
        const uint4* s = (const uint4*)&qp[(size_t)d * LSP + i0 + c];
        uint4* t = (uint4*)&Qs[d * QI + c];
        #pragma unroll
        for (int j = 0; j < 8; j++) t[j] = s[j];
    }
    __syncthreads();

    unsigned int qa[2][4][4];
    #pragma unroll
    for (int mi = 0; mi < 2; mi++)
        #pragma unroll
        for (int ks = 0; ks < 4; ks++) {
            int drow = ks * 16 + (lg >> 1) * 8 + lr;
            int icol = ibase + mi * 16 + (lg & 1) * 8;
            LDSM4T(qa[mi][ks][0], qa[mi][ks][1], qa[mi][ks][2], qa[mi][ks][3],
                   smem_u32(&Qs[drow * QI + icol]));
        }

    float oacc[2][8][4] = {};
    float rl[2] = {0.f, 0.f}, rh[2] = {0.f, 0.f};

    for (int kt = 0; kt < 16; kt++) {
        int s = kt & 1;
        CP_WAIT0();
        __syncthreads();
        if (kt < 15) stageKV(s ^ 1, kt + 1);

        unsigned int kb = kbuf0 + s * KV_BYTES;
        unsigned int vb = vbuf0 + s * KV_BYTES;

        // S: both m-tiles share each K fragment
        float sacc[2][8][4] = {};
        #pragma unroll
        for (int ks = 0; ks < 4; ks++) {
            #pragma unroll
            for (int jp = 0; jp < 4; jp++) {
                int drow = ks * 16 + (lg & 1) * 8 + lr;
                int jcol = jp * 16 + (lg >> 1) * 8;
                unsigned int b0, b1, b2, b3;
                LDSM4T(b0, b1, b2, b3, kb + drow * (KJ * 2) + jcol * 2);
                #pragma unroll
                for (int mi = 0; mi < 2; mi++) {
                    MMA16816(sacc[mi][jp * 2],     qa[mi][ks], b0, b1);
                    MMA16816(sacc[mi][jp * 2 + 1], qa[mi][ks], b2, b3);
                }
            }
        }

        unsigned int pa[2][4][4];
        #pragma unroll
        for (int mi = 0; mi < 2; mi++)
            #pragma unroll
            for (int t = 0; t < 8; t++) {
                float e0 = __expf(sacc[mi][t][0] * 0.125f);
                float e1 = __expf(sacc[mi][t][1] * 0.125f);
                float e2 = __expf(sacc[mi][t][2] * 0.125f);
                float e3 = __expf(sacc[mi][t][3] * 0.125f);
                rl[mi] += e0 + e1;
                rh[mi] += e2 + e3;
                pa[mi][t >> 1][(t & 1) * 2]     = packbf2(e0, e1);
                pa[mi][t >> 1][(t & 1) * 2 + 1] = packbf2(e2, e3);
            }

        // PV: both m-tiles share each V fragment
        #pragma unroll
        for (int ks = 0; ks < 4; ks++) {
            #pragma unroll
            for (int dp = 0; dp < 4; dp++) {
                int drow = dp * 16 + (lg >> 1) * 8 + lr;
                int jcol = ks * 16 + (lg & 1) * 8;
                unsigned int b0, b1, b2, b3;
                LDSM4(b0, b1, b2, b3, vb + drow * (KJ * 2) + jcol * 2);
                #pragma unroll
                for (int mi = 0; mi < 2; mi++) {
                    MMA16816(oacc[mi][dp * 2],     pa[mi][ks], b0, b1);
                    MMA16816(oacc[mi][dp * 2 + 1], pa[mi][ks], b2, b3);
                }
            }
        }
    }

    float il[2], ih[2];
    #pragma unroll
    for (int mi = 0; mi < 2; mi++) {
        rl[mi] += __shfl_xor_sync(~0u, rl[mi], 1); rl[mi] += __shfl_xor_sync(~0u, rl[mi], 2);
        rh[mi] += __shfl_xor_sync(~0u, rh[mi], 1); rh[mi] += __shfl_xor_sync(~0u, rh[mi], 2);
        il[mi] = 1.f / rl[mi];
        ih[mi] = 1.f / rh[mi];
    }

    __syncthreads();
    #pragma unroll
    for (int mi = 0; mi < 2; mi++) {
        int ib = ibase + mi * 16;
        #pragma unroll
        for (int t = 0; t < 8; t++) {
            int dcol = t * 8 + qtid * 2;
            Qs[dcol * QI + ib + gid]           = __float2bfloat16(oacc[mi][t][0] * il[mi]);
            Qs[(dcol + 1) * QI + ib + gid]     = __float2bfloat16(oacc[mi][t][1] * il[mi]);
            Qs[dcol * QI + ib + gid + 8]       = __float2bfloat16(oacc[mi][t][2] * ih[mi]);
            Qs[(dcol + 1) * QI + ib + gid + 8] = __float2bfloat16(oacc[mi][t][3] * ih[mi]);
        }
    }
    __syncthreads();

    {
        int d = tid >> 1, c = (tid & 1) * 64;
        const uint4* s = (const uint4*)&Qs[d * QI + c];
        uint4* t = (uint4*)&op[(size_t)d * LSP + i0 + c];
        #pragma unroll
        for (int j = 0; j < 8; j++) t[j] = s[j];
    }
}

// ---------------- launch ----------------
extern "C" void kernel_launch(void* const* d_in, const int* in_sizes, int n_in,
                              void* d_out, int out_size)
{
    const float* x   = (const float*)d_in[0];
    const float* ctx = (const float*)d_in[1];
    const float* nqw = (const float*)d_in[2];
    const float* nqb = (const float*)d_in[3];
    const float* nkw = (const float*)d_in[4];
    const float* nkb = (const float*)d_in[5];
    const float* cqw = (const float*)d_in[6];
    const float* cqb = (const float*)d_in[7];
    const float* ckw = (const float*)d_in[8];
    const float* ckb = (const float*)d_in[9];
    const float* pw  = (const float*)d_in[10];
    const float* pb  = (const float*)d_in[11];
    float* out = (float*)d_out;

    bf16 *xn, *cn, *q, *kv, *o, *wq, *wkv, *wp;
    cudaGetSymbolAddress((void**)&xn,  g_xn);
    cudaGetSymbolAddress((void**)&cn,  g_cn);
    cudaGetSymbolAddress((void**)&q,   g_q);
    cudaGetSymbolAddress((void**)&kv,  g_kv);
    cudaGetSymbolAddress((void**)&o,   g_o);
    cudaGetSymbolAddress((void**)&wq,  g_wq);
    cudaGetSymbolAddress((void**)&wkv, g_wkv);
    cudaGetSymbolAddress((void**)&wp,  g_wp);

    const int gsmem = 6 * A_ST;   // 98304 B
    cudaFuncSetAttribute(gemm_qkv,  cudaFuncAttributeMaxDynamicSharedMemorySize, gsmem);
    cudaFuncSetAttribute(gemm_proj, cudaFuncAttributeMaxDynamicSharedMemorySize, gsmem);
    cudaFuncSetAttribute(attn_mma,  cudaFuncAttributeMaxDynamicSharedMemorySize, ATTN_SMEM);

    const int nq = CCH * CCH / 4, nkv = 2 * CCH * CCH / 4;
    const int cvt_blocks = (nq + nkv + nq + 255) / 256;   // 1024

    head_kernel<<<2 * BATCH * 32 + cvt_blocks, 256>>>(
        x, nqw, nqb, xn, ctx, nkw, nkb, cn,
        cqw, wq, nq, ckw, wkv, nkv, pw, wp, nq);

    gemm_qkv<<<dim3(8, 12, BATCH), 256, gsmem>>>(xn, cn, wq, wkv, cqb, ckb, q, kv);

    attn_mma<<<dim3(8, NHEADS, BATCH), 128, ATTN_SMEM>>>(q, kv, o);

    gemm_proj<<<dim3(8, 4, BATCH), 256, gsmem>>>(o, wp, pb, x, out);
}

// round 16
// speedup vs baseline: 1.0467x; 1.0467x over previous
#include <cuda_runtime.h>
#include <cuda_bf16.h>
#include <math.h>
#include <cstdint>

#define BATCH  16
#define CCH    512
#define LSP    1024
#define NHEADS 8

typedef __nv_bfloat16 bf16;
typedef __nv_bfloat162 bf162;

// ---------------- scratch (static device globals; no allocs) ----------------
__device__ bf16 g_xn[BATCH * CCH * LSP];
__device__ bf16 g_cn[BATCH * CCH * LSP];
__device__ bf16 g_q [BATCH * CCH * LSP];
__device__ bf16 g_kv[BATCH * 2 * CCH * LSP];
__device__ bf16 g_o [BATCH * CCH * LSP];
__device__ bf16 g_wq [CCH * CCH];
__device__ bf16 g_wkv[2 * CCH * CCH];
__device__ bf16 g_wp [CCH * CCH];

// ---------------- PTX helpers ----------------
__device__ __forceinline__ unsigned int smem_u32(const void* p) {
    return (unsigned int)__cvta_generic_to_shared(p);
}
#define CP_ASYNC16(dst, src) \
    asm volatile("cp.async.cg.shared.global [%0], [%1], 16;\n" :: "r"(dst), "l"(src))
#define CP_COMMIT() asm volatile("cp.async.commit_group;\n" ::)
#define CP_WAIT1()  asm volatile("cp.async.wait_group 1;\n" ::)
#define CP_WAIT0()  asm volatile("cp.async.wait_group 0;\n" ::)
#define LDSM4(r0,r1,r2,r3,addr) \
    asm volatile("ldmatrix.sync.aligned.m8n8.x4.shared.b16 {%0,%1,%2,%3},[%4];" \
        : "=r"(r0),"=r"(r1),"=r"(r2),"=r"(r3) : "r"(addr))
#define LDSM4T(r0,r1,r2,r3,addr) \
    asm volatile("ldmatrix.sync.aligned.m8n8.x4.trans.shared.b16 {%0,%1,%2,%3},[%4];" \
        : "=r"(r0),"=r"(r1),"=r"(r2),"=r"(r3) : "r"(addr))
#define MMA16816(c,a,b0,b1) \
    asm volatile("mma.sync.aligned.m16n8k16.row.col.f32.bf16.bf16.f32 " \
        "{%0,%1,%2,%3},{%4,%5,%6,%7},{%8,%9},{%0,%1,%2,%3};" \
        : "+f"(c[0]),"+f"(c[1]),"+f"(c[2]),"+f"(c[3]) \
        : "r"(a[0]),"r"(a[1]),"r"(a[2]),"r"(a[3]),"r"(b0),"r"(b1))

__device__ __forceinline__ unsigned int packbf2(float a, float b) {
    bf162 t = __floats2bfloat162_rn(a, b);
    return *(unsigned int*)&t;
}

// ---------------- head kernel: 512-thr reg-cached GroupNorm + weight cvt ----
// blocks [0, 1024): GN (one per batch*group*2 tensors); blocks >= 1024: cvt.
__global__ __launch_bounds__(512) void head_kernel(
    const float* __restrict__ x0, const float* __restrict__ w0,
    const float* __restrict__ b0, bf16* __restrict__ out0,
    const float* __restrict__ x1, const float* __restrict__ w1,
    const float* __restrict__ b1, bf16* __restrict__ out1,
    const float* __restrict__ cs0, bf16* cd0, int n0,
    const float* __restrict__ cs1, bf16* cd1, int n1,
    const float* __restrict__ cs2, bf16* cd2, int n2)
{
    int bg = blockIdx.x;
    int tid = threadIdx.x;

    if (bg >= 2 * BATCH * 32) {
        int i = (bg - 2 * BATCH * 32) * 512 + tid;
        const float* src; bf16* dst;
        if (i < n0)                { src = cs0; dst = cd0; }
        else if (i < n0 + n1)      { i -= n0; src = cs1; dst = cd1; }
        else if (i < n0 + n1 + n2) { i -= n0 + n1; src = cs2; dst = cd2; }
        else return;
        float4 v = ((const float4*)src)[i];
        ((bf162*)dst)[2 * i]     = __floats2bfloat162_rn(v.x, v.y);
        ((bf162*)dst)[2 * i + 1] = __floats2bfloat162_rn(v.z, v.w);
        return;
    }

    const float* x; const float* w; const float* bb; bf16* out;
    if (bg < BATCH * 32) { x = x0; w = w0; bb = b0; out = out0; }
    else { bg -= BATCH * 32; x = x1; w = w1; bb = b1; out = out1; }
    int g = bg & 31;
    const float4* x4 = (const float4*)(x + (size_t)bg * 16384);
    bf162*        o2 = (bf162*)(out + (size_t)bg * 16384);

    // single pass: 8 float4 (32 floats) per thread cached in registers
    float4 v[8];
    #pragma unroll
    for (int t = 0; t < 8; t++) v[t] = x4[tid + t * 512];

    float s = 0.f, ss = 0.f;
    #pragma unroll
    for (int t = 0; t < 8; t++) {
        s  += v[t].x + v[t].y + v[t].z + v[t].w;
        ss += v[t].x*v[t].x + v[t].y*v[t].y + v[t].z*v[t].z + v[t].w*v[t].w;
    }
    __shared__ float rs[16], rss[16];
    #pragma unroll
    for (int o = 16; o; o >>= 1) {
        s  += __shfl_xor_sync(~0u, s, o);
        ss += __shfl_xor_sync(~0u, ss, o);
    }
    if ((tid & 31) == 0) { rs[tid >> 5] = s; rss[tid >> 5] = ss; }
    __syncthreads();
    if (tid < 32) {
        s  = (tid < 16) ? rs[tid]  : 0.f;
        ss = (tid < 16) ? rss[tid] : 0.f;
        #pragma unroll
        for (int o = 8; o; o >>= 1) {
            s  += __shfl_xor_sync(~0u, s, o);
            ss += __shfl_xor_sync(~0u, ss, o);
        }
        if (tid == 0) { rs[0] = s; rss[0] = ss; }
    }
    __syncthreads();
    float mean = rs[0] * (1.f / 16384.f);
    float var  = rss[0] * (1.f / 16384.f) - mean * mean;
    float inv  = rsqrtf(var + 1e-5f);

    #pragma unroll
    for (int t = 0; t < 8; t++) {
        int i = tid + t * 512;
        int c = g * 16 + (i >> 8);
        float sc = w[c] * inv;
        float sh = bb[c] - mean * sc;
        o2[2 * i]     = __floats2bfloat162_rn(v[t].x * sc + sh, v[t].y * sc + sh);
        o2[2 * i + 1] = __floats2bfloat162_rn(v[t].z * sc + sh, v[t].w * sc + sh);
    }
}

// ---------------- conv1x1 GEMM core (R11/R9 winner, unchanged) --------------
#define A_ST 16384
#define B_OFF (3 * A_ST)

template<bool BF16OUT>
__device__ __forceinline__ void gemm_body(const bf16* __restrict__ in,
                                          const bf16* __restrict__ W,
                                          const float* __restrict__ bias,
                                          const float* __restrict__ resid,
                                          void* __restrict__ outp, int O,
                                          int b, int o0, int l0, char* smraw)
{
    const unsigned int sbase = smem_u32(smraw);
    int tid = threadIdx.x, wid = tid >> 5, lane = tid & 31;
    int wm = wid >> 1, wn = wid & 1;
    int gid = lane >> 2, qtid = lane & 3;
    int lg = lane >> 3, lr = lane & 7;

    const bf16* Xb = in + (size_t)b * CCH * LSP;

    auto stage = [&](int s, int kc) {
        const bf16* Aw = W  + (size_t)o0 * CCH + kc * 64;
        const bf16* Bx = Xb + (size_t)(kc * 64) * LSP + l0;
        #pragma unroll
        for (int t = 0; t < 4; t++) {
            int idx = tid + t * 256;
            int ar = idx >> 3, g = idx & 7;
            unsigned int dst = sbase + s * A_ST + ar * 128 + ((g ^ (ar & 7)) << 4);
            CP_ASYNC16(dst, Aw + (size_t)ar * CCH + g * 8);
        }
        #pragma unroll
        for (int t = 0; t < 4; t++) {
            int idx = tid + t * 256;
            int br = idx >> 4, g = idx & 15;
            unsigned int dst = sbase + B_OFF + s * A_ST + br * 256 + ((g ^ (br & 7)) << 4);
            CP_ASYNC16(dst, Bx + (size_t)br * LSP + g * 8);
        }
        CP_COMMIT();
    };

    float acc[2][8][4] = {};

    const int T = CCH / 64;
    stage(0, 0);
    stage(1, 1);

    for (int i = 0; i < T; i++) {
        int s = i % 3;
        if (i == T - 1) { CP_WAIT0(); } else { CP_WAIT1(); }
        __syncthreads();
        if (i + 2 < T) stage((i + 2) % 3, i + 2);

        unsigned int abase = sbase + s * A_ST;
        unsigned int bbase = sbase + B_OFF + s * A_ST;
        #pragma unroll
        for (int ks = 0; ks < 4; ks++) {
            unsigned int af[2][4];
            #pragma unroll
            for (int mi = 0; mi < 2; mi++) {
                int mrow = wm * 32 + mi * 16 + (lg & 1) * 8 + lr;
                int kg   = (ks * 16 + (lg >> 1) * 8) >> 3;
                LDSM4(af[mi][0], af[mi][1], af[mi][2], af[mi][3],
                      abase + mrow * 128 + ((kg ^ (mrow & 7)) << 4));
            }
            #pragma unroll
            for (int np = 0; np < 4; np++) {
                int krow = ks * 16 + (lg & 1) * 8 + lr;
                int ng   = (wn * 64 + np * 16 + (lg >> 1) * 8) >> 3;
                unsigned int b0, b1, b2, b3;
                LDSM4T(b0, b1, b2, b3,
                       bbase + krow * 256 + ((ng ^ (krow & 7)) << 4));
                #pragma unroll
                for (int mi = 0; mi < 2; mi++) {
                    MMA16816(acc[mi][np * 2],     af[mi], b0, b1);
                    MMA16816(acc[mi][np * 2 + 1], af[mi], b2, b3);
                }
            }
        }
    }

    #pragma unroll
    for (int mi = 0; mi < 2; mi++) {
        int r0 = wm * 32 + mi * 16 + gid;
        float bi0 = bias[o0 + r0];
        float bi1 = bias[o0 + r0 + 8];
        size_t row0 = ((size_t)b * O + o0 + r0) * LSP + l0;
        size_t row1 = row0 + (size_t)8 * LSP;
        #pragma unroll
        for (int t = 0; t < 8; t++) {
            int c = wn * 64 + t * 8 + qtid * 2;
            if (BF16OUT) {
                bf16* ob = (bf16*)outp;
                *(unsigned int*)&ob[row0 + c] = packbf2(acc[mi][t][0] + bi0, acc[mi][t][1] + bi0);
                *(unsigned int*)&ob[row1 + c] = packbf2(acc[mi][t][2] + bi1, acc[mi][t][3] + bi1);
            } else {
                float* of = (float*)outp;
                float2 rv0 = *(const float2*)&resid[row0 + c];
                float2 rv1 = *(const float2*)&resid[row1 + c];
                float2 v0 = {acc[mi][t][0] + bi0 + rv0.x, acc[mi][t][1] + bi0 + rv0.y};
                float2 v1 = {acc[mi][t][2] + bi1 + rv1.x, acc[mi][t][3] + bi1 + rv1.y};
                *(float2*)&of[row0 + c] = v0;
                *(float2*)&of[row1 + c] = v1;
            }
        }
    }
}

// merged q + kv GEMM: y in [0,4) -> q from xn; y in [4,12) -> kv from cn
__global__ __launch_bounds__(256, 2) void gemm_qkv(const bf16* __restrict__ xn,
                                                   const bf16* __restrict__ cn,
                                                   const bf16* __restrict__ wq,
                                                   const bf16* __restrict__ wkv,
                                                   const float* __restrict__ qb,
                                                   const float* __restrict__ kvb,
                                                   bf16* __restrict__ qo,
                                                   bf16* __restrict__ kvo)
{
    extern __shared__ char smraw[];
    int y = blockIdx.y;
    if (y < 4)
        gemm_body<true>(xn, wq, qb, nullptr, qo, CCH,
                        blockIdx.z, y * 128, blockIdx.x * 128, smraw);
    else
        gemm_body<true>(cn, wkv, kvb, nullptr, kvo, 2 * CCH,
                        blockIdx.z, (y - 4) * 128, blockIdx.x * 128, smraw);
}

__global__ __launch_bounds__(256, 2) void gemm_proj(const bf16* __restrict__ in,
                                                    const bf16* __restrict__ W,
                                                    const float* __restrict__ bias,
                                                    const float* __restrict__ resid,
                                                    float* __restrict__ outp)
{
    extern __shared__ char smraw[];
    gemm_body<false>(in, W, bias, resid, outp, CCH,
                     blockIdx.z, blockIdx.y * 128, blockIdx.x * 128, smraw);
}

// ---------------- attention (R10 winner, 256 thr, unchanged) ----------------
#define QI 136
#define KJ 72
#define Q_BYTES (64 * QI * 2)
#define KV_BYTES (64 * KJ * 2)
#define ATTN_SMEM (Q_BYTES + 4 * KV_BYTES)

__global__ __launch_bounds__(256, 2) void attn_mma(const bf16* __restrict__ qb,
                                                   const bf16* __restrict__ kvb,
                                                   bf16* __restrict__ ob)
{
    extern __shared__ char asmraw[];
    bf16* Qs = (bf16*)asmraw;
    const unsigned int sb = smem_u32(asmraw);
    const unsigned int kbuf0 = sb + Q_BYTES;
    const unsigned int vbuf0 = sb + Q_BYTES + 2 * KV_BYTES;

    int i0 = blockIdx.x * 128;
    int h  = blockIdx.y;
    int b  = blockIdx.z;
    int tid = threadIdx.x, wid = tid >> 5, lane = tid & 31;
    int gid = lane >> 2, qtid = lane & 3;
    int ibase = wid * 16;
    int lg = lane >> 3, lr = lane & 7;

    const bf16* qp = qb  + ((size_t)b * CCH     + h * 64) * LSP;
    const bf16* kp = kvb + ((size_t)b * 2 * CCH + h * 64) * LSP;
    const bf16* vp = kvb + ((size_t)b * 2 * CCH + CCH + h * 64) * LSP;
    bf16*       op = ob  + ((size_t)b * CCH     + h * 64) * LSP;

    int dk = tid >> 2, ck4 = (tid & 3);

    auto stageKV = [&](int s, int kt) {
        const bf16* ks_ = kp + (size_t)dk * LSP + kt * 64 + ck4 * 16;
        const bf16* vs_ = vp + (size_t)dk * LSP + kt * 64 + ck4 * 16;
        unsigned int ko = kbuf0 + s * KV_BYTES + dk * (KJ * 2) + ck4 * 32;
        unsigned int vo = vbuf0 + s * KV_BYTES + dk * (KJ * 2) + ck4 * 32;
        CP_ASYNC16(ko,      ks_);
        CP_ASYNC16(ko + 16, ks_ + 8);
        CP_ASYNC16(vo,      vs_);
        CP_ASYNC16(vo + 16, vs_ + 8);
        CP_COMMIT();
    };

    stageKV(0, 0);

    {
        int d = tid >> 2, c = (tid & 3) * 32;
        const uint4* s = (const uint4*)&qp[(size_t)d * LSP + i0 + c];
        uint4* t = (uint4*)&Qs[d * QI + c];
        t[0] = s[0]; t[1] = s[1]; t[2] = s[2]; t[3] = s[3];
    }
    __syncthreads();

    unsigned int qa[4][4];
    #pragma unroll
    for (int ks = 0; ks < 4; ks++) {
        int drow = ks * 16 + (lg >> 1) * 8 + lr;
        int icol = ibase + (lg & 1) * 8;
        unsigned int a = smem_u32(&Qs[drow * QI + icol]);
        LDSM4T(qa[ks][0], qa[ks][1], qa[ks][2], qa[ks][3], a);
    }

    float oacc[8][4] = {};
    float rl = 0.f, rh = 0.f;

    for (int kt = 0; kt < 16; kt++) {
        int s = kt & 1;
        CP_WAIT0();
        __syncthreads();
        if (kt < 15) stageKV(s ^ 1, kt + 1);

        unsigned int kb = kbuf0 + s * KV_BYTES;
        unsigned int vb = vbuf0 + s * KV_BYTES;

        float sacc[8][4] = {};
        #pragma unroll
        for (int ks = 0; ks < 4; ks++) {
            #pragma unroll
            for (int jp = 0; jp < 4; jp++) {
                int drow = ks * 16 + (lg & 1) * 8 + lr;
                int jcol = jp * 16 + (lg >> 1) * 8;
                unsigned int a = kb + drow * (KJ * 2) + jcol * 2;
                unsigned int b0, b1, b2, b3;
                LDSM4T(b0, b1, b2, b3, a);
                MMA16816(sacc[jp * 2],     qa[ks], b0, b1);
                MMA16816(sacc[jp * 2 + 1], qa[ks], b2, b3);
            }
        }

        unsigned int pa[4][4];
        #pragma unroll
        for (int t = 0; t < 8; t++) {
            float e0 = __expf(sacc[t][0] * 0.125f);
            float e1 = __expf(sacc[t][1] * 0.125f);
            float e2 = __expf(sacc[t][2] * 0.125f);
            float e3 = __expf(sacc[t][3] * 0.125f);
            rl += e0 + e1;
            rh += e2 + e3;
            pa[t >> 1][(t & 1) * 2]     = packbf2(e0, e1);
            pa[t >> 1][(t & 1) * 2 + 1] = packbf2(e2, e3);
        }

        #pragma unroll
        for (int ks = 0; ks < 4; ks++) {
            #pragma unroll
            for (int dp = 0; dp < 4; dp++) {
                int drow = dp * 16 + (lg >> 1) * 8 + lr;
                int jcol = ks * 16 + (lg & 1) * 8;
                unsigned int a = vb + drow * (KJ * 2) + jcol * 2;
                unsigned int b0, b1, b2, b3;
                LDSM4(b0, b1, b2, b3, a);
                MMA16816(oacc[dp * 2],     pa[ks], b0, b1);
                MMA16816(oacc[dp * 2 + 1], pa[ks], b2, b3);
            }
        }
    }

    rl += __shfl_xor_sync(~0u, rl, 1); rl += __shfl_xor_sync(~0u, rl, 2);
    rh += __shfl_xor_sync(~0u, rh, 1); rh += __shfl_xor_sync(~0u, rh, 2);
    float il = 1.f / rl, ih = 1.f / rh;

    __syncthreads();
    #pragma unroll
    for (int t = 0; t < 8; t++) {
        int dcol = t * 8 + qtid * 2;
        Qs[dcol * QI + ibase + gid]           = __float2bfloat16(oacc[t][0] * il);
        Qs[(dcol + 1) * QI + ibase + gid]     = __float2bfloat16(oacc[t][1] * il);
        Qs[dcol * QI + ibase + gid + 8]       = __float2bfloat16(oacc[t][2] * ih);
        Qs[(dcol + 1) * QI + ibase + gid + 8] = __float2bfloat16(oacc[t][3] * ih);
    }
    __syncthreads();

    {
        int d = tid >> 2, c = (tid & 3) * 32;
        const uint4* s = (const uint4*)&Qs[d * QI + c];
        uint4* t = (uint4*)&op[(size_t)d * LSP + i0 + c];
        t[0] = s[0]; t[1] = s[1]; t[2] = s[2]; t[3] = s[3];
    }
}

// ---------------- launch ----------------
extern "C" void kernel_launch(void* const* d_in, const int* in_sizes, int n_in,
                              void* d_out, int out_size)
{
    const float* x   = (const float*)d_in[0];
    const float* ctx = (const float*)d_in[1];
    const float* nqw = (const float*)d_in[2];
    const float* nqb = (const float*)d_in[3];
    const float* nkw = (const float*)d_in[4];
    const float* nkb = (const float*)d_in[5];
    const float* cqw = (const float*)d_in[6];
    const float* cqb = (const float*)d_in[7];
    const float* ckw = (const float*)d_in[8];
    const float* ckb = (const float*)d_in[9];
    const float* pw  = (const float*)d_in[10];
    const float* pb  = (const float*)d_in[11];
    float* out = (float*)d_out;

    bf16 *xn, *cn, *q, *kv, *o, *wq, *wkv, *wp;
    cudaGetSymbolAddress((void**)&xn,  g_xn);
    cudaGetSymbolAddress((void**)&cn,  g_cn);
    cudaGetSymbolAddress((void**)&q,   g_q);
    cudaGetSymbolAddress((void**)&kv,  g_kv);
    cudaGetSymbolAddress((void**)&o,   g_o);
    cudaGetSymbolAddress((void**)&wq,  g_wq);
    cudaGetSymbolAddress((void**)&wkv, g_wkv);
    cudaGetSymbolAddress((void**)&wp,  g_wp);

    const int gsmem = 6 * A_ST;   // 98304 B
    cudaFuncSetAttribute(gemm_qkv,  cudaFuncAttributeMaxDynamicSharedMemorySize, gsmem);
    cudaFuncSetAttribute(gemm_proj, cudaFuncAttributeMaxDynamicSharedMemorySize, gsmem);
    cudaFuncSetAttribute(attn_mma,  cudaFuncAttributeMaxDynamicSharedMemorySize, ATTN_SMEM);

    const int nq = CCH * CCH / 4, nkv = 2 * CCH * CCH / 4;
    const int cvt_blocks = (nq + nkv + nq + 511) / 512;   // 512

    head_kernel<<<2 * BATCH * 32 + cvt_blocks, 512>>>(
        x, nqw, nqb, xn, ctx, nkw, nkb, cn,
        cqw, wq, nq, ckw, wkv, nkv, pw, wp, nq);

    gemm_qkv<<<dim3(8, 12, BATCH), 256, gsmem>>>(xn, cn, wq, wkv, cqb, ckb, q, kv);

    attn_mma<<<dim3(8, NHEADS, BATCH), 256, ATTN_SMEM>>>(q, kv, o);

    gemm_proj<<<dim3(8, 4, BATCH), 256, gsmem>>>(o, wp, pb, x, out);
}

// round 17
// speedup vs baseline: 1.0762x; 1.0282x over previous
#include <cuda_runtime.h>
#include <cuda_bf16.h>
#include <math.h>
#include <cstdint>

#define BATCH  16
#define CCH    512
#define LSP    1024
#define NHEADS 8

typedef __nv_bfloat16 bf16;
typedef __nv_bfloat162 bf162;

// ---------------- scratch (static device globals; no allocs) ----------------
__device__ bf16 g_xn[BATCH * CCH * LSP];
__device__ bf16 g_cn[BATCH * CCH * LSP];
__device__ bf16 g_q [BATCH * CCH * LSP];
__device__ bf16 g_kv[BATCH * 2 * CCH * LSP];
__device__ bf16 g_o [BATCH * CCH * LSP];
__device__ bf16 g_wq [CCH * CCH];
__device__ bf16 g_wkv[2 * CCH * CCH];
__device__ bf16 g_wp [CCH * CCH];
__device__ unsigned int g_flag[BATCH * 8];   // per (b, l-tile) attn completion count

// ---------------- PTX helpers ----------------
__device__ __forceinline__ unsigned int smem_u32(const void* p) {
    return (unsigned int)__cvta_generic_to_shared(p);
}
#define CP_ASYNC16(dst, src) \
    asm volatile("cp.async.cg.shared.global [%0], [%1], 16;\n" :: "r"(dst), "l"(src))
#define CP_COMMIT() asm volatile("cp.async.commit_group;\n" ::)
#define CP_WAIT1()  asm volatile("cp.async.wait_group 1;\n" ::)
#define CP_WAIT0()  asm volatile("cp.async.wait_group 0;\n" ::)
#define LDSM4(r0,r1,r2,r3,addr) \
    asm volatile("ldmatrix.sync.aligned.m8n8.x4.shared.b16 {%0,%1,%2,%3},[%4];" \
        : "=r"(r0),"=r"(r1),"=r"(r2),"=r"(r3) : "r"(addr))
#define LDSM4T(r0,r1,r2,r3,addr) \
    asm volatile("ldmatrix.sync.aligned.m8n8.x4.trans.shared.b16 {%0,%1,%2,%3},[%4];" \
        : "=r"(r0),"=r"(r1),"=r"(r2),"=r"(r3) : "r"(addr))
#define MMA16816(c,a,b0,b1) \
    asm volatile("mma.sync.aligned.m16n8k16.row.col.f32.bf16.bf16.f32 " \
        "{%0,%1,%2,%3},{%4,%5,%6,%7},{%8,%9},{%0,%1,%2,%3};" \
        : "+f"(c[0]),"+f"(c[1]),"+f"(c[2]),"+f"(c[3]) \
        : "r"(a[0]),"r"(a[1]),"r"(a[2]),"r"(a[3]),"r"(b0),"r"(b1))

__device__ __forceinline__ unsigned int packbf2(float a, float b) {
    bf162 t = __floats2bfloat162_rn(a, b);
    return *(unsigned int*)&t;
}

// ---------------- head kernel: reg-cached GroupNorm + weight cvt + flag reset
__global__ __launch_bounds__(256) void head_kernel(
    const float* __restrict__ x0, const float* __restrict__ w0,
    const float* __restrict__ b0, bf16* __restrict__ out0,
    const float* __restrict__ x1, const float* __restrict__ w1,
    const float* __restrict__ b1, bf16* __restrict__ out1,
    const float* __restrict__ cs0, bf16* cd0, int n0,
    const float* __restrict__ cs1, bf16* cd1, int n1,
    const float* __restrict__ cs2, bf16* cd2, int n2)
{
    int bg = blockIdx.x;
    int tid = threadIdx.x;

    if (bg == 0 && tid < BATCH * 8) g_flag[tid] = 0;   // reset attn->proj flags

    if (bg >= 2 * BATCH * 32) {
        int i = (bg - 2 * BATCH * 32) * 256 + tid;
        const float* src; bf16* dst;
        if (i < n0)                { src = cs0; dst = cd0; }
        else if (i < n0 + n1)      { i -= n0; src = cs1; dst = cd1; }
        else if (i < n0 + n1 + n2) { i -= n0 + n1; src = cs2; dst = cd2; }
        else return;
        float4 v = ((const float4*)src)[i];
        ((bf162*)dst)[2 * i]     = __floats2bfloat162_rn(v.x, v.y);
        ((bf162*)dst)[2 * i + 1] = __floats2bfloat162_rn(v.z, v.w);
        return;
    }

    const float* x; const float* w; const float* bb; bf16* out;
    if (bg < BATCH * 32) { x = x0; w = w0; bb = b0; out = out0; }
    else { bg -= BATCH * 32; x = x1; w = w1; bb = b1; out = out1; }
    int g = bg & 31;
    const float4* x4 = (const float4*)(x + (size_t)bg * 16384);
    bf162*        o2 = (bf162*)(out + (size_t)bg * 16384);

    float4 v[16];
    #pragma unroll
    for (int t = 0; t < 16; t++) v[t] = x4[tid + t * 256];

    float s = 0.f, ss = 0.f;
    #pragma unroll
    for (int t = 0; t < 16; t++) {
        s  += v[t].x + v[t].y + v[t].z + v[t].w;
        ss += v[t].x*v[t].x + v[t].y*v[t].y + v[t].z*v[t].z + v[t].w*v[t].w;
    }
    __shared__ float rs[8], rss[8];
    #pragma unroll
    for (int o = 16; o; o >>= 1) {
        s  += __shfl_xor_sync(~0u, s, o);
        ss += __shfl_xor_sync(~0u, ss, o);
    }
    if ((tid & 31) == 0) { rs[tid >> 5] = s; rss[tid >> 5] = ss; }
    __syncthreads();
    if (tid < 32) {
        s  = (tid < 8) ? rs[tid]  : 0.f;
        ss = (tid < 8) ? rss[tid] : 0.f;
        #pragma unroll
        for (int o = 4; o; o >>= 1) {
            s  += __shfl_xor_sync(~0u, s, o);
            ss += __shfl_xor_sync(~0u, ss, o);
        }
        if (tid == 0) { rs[0] = s; rss[0] = ss; }
    }
    __syncthreads();
    float mean = rs[0] * (1.f / 16384.f);
    float var  = rss[0] * (1.f / 16384.f) - mean * mean;
    float inv  = rsqrtf(var + 1e-5f);

    #pragma unroll
    for (int t = 0; t < 16; t++) {
        int i = tid + t * 256;
        int c = g * 16 + (i >> 8);
        float sc = w[c] * inv;
        float sh = bb[c] - mean * sc;
        o2[2 * i]     = __floats2bfloat162_rn(v[t].x * sc + sh, v[t].y * sc + sh);
        o2[2 * i + 1] = __floats2bfloat162_rn(v[t].z * sc + sh, v[t].w * sc + sh);
    }
}

// ---------------- conv1x1 GEMM core (R9/R11 winner, unchanged) --------------
#define A_ST 16384
#define B_OFF (3 * A_ST)

template<bool BF16OUT>
__device__ __forceinline__ void gemm_body(const bf16* __restrict__ in,
                                          const bf16* __restrict__ W,
                                          const float* __restrict__ bias,
                                          const float* __restrict__ resid,
                                          void* __restrict__ outp, int O,
                                          int b, int o0, int l0, char* smraw)
{
    const unsigned int sbase = smem_u32(smraw);
    int tid = threadIdx.x, wid = tid >> 5, lane = tid & 31;
    int wm = wid >> 1, wn = wid & 1;
    int gid = lane >> 2, qtid = lane & 3;
    int lg = lane >> 3, lr = lane & 7;

    const bf16* Xb = in + (size_t)b * CCH * LSP;

    auto stage = [&](int s, int kc) {
        const bf16* Aw = W  + (size_t)o0 * CCH + kc * 64;
        const bf16* Bx = Xb + (size_t)(kc * 64) * LSP + l0;
        #pragma unroll
        for (int t = 0; t < 4; t++) {
            int idx = tid + t * 256;
            int ar = idx >> 3, g = idx & 7;
            unsigned int dst = sbase + s * A_ST + ar * 128 + ((g ^ (ar & 7)) << 4);
            CP_ASYNC16(dst, Aw + (size_t)ar * CCH + g * 8);
        }
        #pragma unroll
        for (int t = 0; t < 4; t++) {
            int idx = tid + t * 256;
            int br = idx >> 4, g = idx & 15;
            unsigned int dst = sbase + B_OFF + s * A_ST + br * 256 + ((g ^ (br & 7)) << 4);
            CP_ASYNC16(dst, Bx + (size_t)br * LSP + g * 8);
        }
        CP_COMMIT();
    };

    float acc[2][8][4] = {};

    const int T = CCH / 64;
    stage(0, 0);
    stage(1, 1);

    for (int i = 0; i < T; i++) {
        int s = i % 3;
        if (i == T - 1) { CP_WAIT0(); } else { CP_WAIT1(); }
        __syncthreads();
        if (i + 2 < T) stage((i + 2) % 3, i + 2);

        unsigned int abase = sbase + s * A_ST;
        unsigned int bbase = sbase + B_OFF + s * A_ST;
        #pragma unroll
        for (int ks = 0; ks < 4; ks++) {
            unsigned int af[2][4];
            #pragma unroll
            for (int mi = 0; mi < 2; mi++) {
                int mrow = wm * 32 + mi * 16 + (lg & 1) * 8 + lr;
                int kg   = (ks * 16 + (lg >> 1) * 8) >> 3;
                LDSM4(af[mi][0], af[mi][1], af[mi][2], af[mi][3],
                      abase + mrow * 128 + ((kg ^ (mrow & 7)) << 4));
            }
            #pragma unroll
            for (int np = 0; np < 4; np++) {
                int krow = ks * 16 + (lg & 1) * 8 + lr;
                int ng   = (wn * 64 + np * 16 + (lg >> 1) * 8) >> 3;
                unsigned int b0, b1, b2, b3;
                LDSM4T(b0, b1, b2, b3,
                       bbase + krow * 256 + ((ng ^ (krow & 7)) << 4));
                #pragma unroll
                for (int mi = 0; mi < 2; mi++) {
                    MMA16816(acc[mi][np * 2],     af[mi], b0, b1);
                    MMA16816(acc[mi][np * 2 + 1], af[mi], b2, b3);
                }
            }
        }
    }

    #pragma unroll
    for (int mi = 0; mi < 2; mi++) {
        int r0 = wm * 32 + mi * 16 + gid;
        float bi0 = bias[o0 + r0];
        float bi1 = bias[o0 + r0 + 8];
        size_t row0 = ((size_t)b * O + o0 + r0) * LSP + l0;
        size_t row1 = row0 + (size_t)8 * LSP;
        #pragma unroll
        for (int t = 0; t < 8; t++) {
            int c = wn * 64 + t * 8 + qtid * 2;
            if (BF16OUT) {
                bf16* ob = (bf16*)outp;
                *(unsigned int*)&ob[row0 + c] = packbf2(acc[mi][t][0] + bi0, acc[mi][t][1] + bi0);
                *(unsigned int*)&ob[row1 + c] = packbf2(acc[mi][t][2] + bi1, acc[mi][t][3] + bi1);
            } else {
                float* of = (float*)outp;
                float2 rv0 = *(const float2*)&resid[row0 + c];
                float2 rv1 = *(const float2*)&resid[row1 + c];
                float2 v0 = {acc[mi][t][0] + bi0 + rv0.x, acc[mi][t][1] + bi0 + rv0.y};
                float2 v1 = {acc[mi][t][2] + bi1 + rv1.x, acc[mi][t][3] + bi1 + rv1.y};
                *(float2*)&of[row0 + c] = v0;
                *(float2*)&of[row1 + c] = v1;
            }
        }
    }
}

// merged q + kv GEMM: y in [0,4) -> q from xn; y in [4,12) -> kv from cn
__global__ __launch_bounds__(256, 2) void gemm_qkv(const bf16* __restrict__ xn,
                                                   const bf16* __restrict__ cn,
                                                   const bf16* __restrict__ wq,
                                                   const bf16* __restrict__ wkv,
                                                   const float* __restrict__ qb,
                                                   const float* __restrict__ kvb,
                                                   bf16* __restrict__ qo,
                                                   bf16* __restrict__ kvo)
{
    extern __shared__ char smraw[];
    int y = blockIdx.y;
    if (y < 4)
        gemm_body<true>(xn, wq, qb, nullptr, qo, CCH,
                        blockIdx.z, y * 128, blockIdx.x * 128, smraw);
    else
        gemm_body<true>(cn, wkv, kvb, nullptr, kvo, 2 * CCH,
                        blockIdx.z, (y - 4) * 128, blockIdx.x * 128, smraw);
}

// ---------------- attention body (R10 winner, as device function) -----------
#define QI 136
#define KJ 72
#define Q_BYTES (64 * QI * 2)
#define KV_BYTES (64 * KJ * 2)
#define ATTN_SMEM (Q_BYTES + 4 * KV_BYTES)

__device__ __forceinline__ void attn_body(const bf16* __restrict__ qb,
                                          const bf16* __restrict__ kvb,
                                          bf16* __restrict__ ob,
                                          int xtile, int h, int b, char* asmraw)
{
    bf16* Qs = (bf16*)asmraw;
    const unsigned int sb = smem_u32(asmraw);
    const unsigned int kbuf0 = sb + Q_BYTES;
    const unsigned int vbuf0 = sb + Q_BYTES + 2 * KV_BYTES;

    int i0 = xtile * 128;
    int tid = threadIdx.x, wid = tid >> 5, lane = tid & 31;
    int gid = lane >> 2, qtid = lane & 3;
    int ibase = wid * 16;
    int lg = lane >> 3, lr = lane & 7;

    const bf16* qp = qb  + ((size_t)b * CCH     + h * 64) * LSP;
    const bf16* kp = kvb + ((size_t)b * 2 * CCH + h * 64) * LSP;
    const bf16* vp = kvb + ((size_t)b * 2 * CCH + CCH + h * 64) * LSP;
    bf16*       op = ob  + ((size_t)b * CCH     + h * 64) * LSP;

    int dk = tid >> 2, ck4 = (tid & 3);

    auto stageKV = [&](int s, int kt) {
        const bf16* ks_ = kp + (size_t)dk * LSP + kt * 64 + ck4 * 16;
        const bf16* vs_ = vp + (size_t)dk * LSP + kt * 64 + ck4 * 16;
        unsigned int ko = kbuf0 + s * KV_BYTES + dk * (KJ * 2) + ck4 * 32;
        unsigned int vo = vbuf0 + s * KV_BYTES + dk * (KJ * 2) + ck4 * 32;
        CP_ASYNC16(ko,      ks_);
        CP_ASYNC16(ko + 16, ks_ + 8);
        CP_ASYNC16(vo,      vs_);
        CP_ASYNC16(vo + 16, vs_ + 8);
        CP_COMMIT();
    };

    stageKV(0, 0);

    {
        int d = tid >> 2, c = (tid & 3) * 32;
        const uint4* s = (const uint4*)&qp[(size_t)d * LSP + i0 + c];
        uint4* t = (uint4*)&Qs[d * QI + c];
        t[0] = s[0]; t[1] = s[1]; t[2] = s[2]; t[3] = s[3];
    }
    __syncthreads();

    unsigned int qa[4][4];
    #pragma unroll
    for (int ks = 0; ks < 4; ks++) {
        int drow = ks * 16 + (lg >> 1) * 8 + lr;
        int icol = ibase + (lg & 1) * 8;
        unsigned int a = smem_u32(&Qs[drow * QI + icol]);
        LDSM4T(qa[ks][0], qa[ks][1], qa[ks][2], qa[ks][3], a);
    }

    float oacc[8][4] = {};
    float rl = 0.f, rh = 0.f;

    for (int kt = 0; kt < 16; kt++) {
        int s = kt & 1;
        CP_WAIT0();
        __syncthreads();
        if (kt < 15) stageKV(s ^ 1, kt + 1);

        unsigned int kb = kbuf0 + s * KV_BYTES;
        unsigned int vb = vbuf0 + s * KV_BYTES;

        float sacc[8][4] = {};
        #pragma unroll
        for (int ks = 0; ks < 4; ks++) {
            #pragma unroll
            for (int jp = 0; jp < 4; jp++) {
                int drow = ks * 16 + (lg & 1) * 8 + lr;
                int jcol = jp * 16 + (lg >> 1) * 8;
                unsigned int a = kb + drow * (KJ * 2) + jcol * 2;
                unsigned int b0, b1, b2, b3;
                LDSM4T(b0, b1, b2, b3, a);
                MMA16816(sacc[jp * 2],     qa[ks], b0, b1);
                MMA16816(sacc[jp * 2 + 1], qa[ks], b2, b3);
            }
        }

        unsigned int pa[4][4];
        #pragma unroll
        for (int t = 0; t < 8; t++) {
            float e0 = __expf(sacc[t][0] * 0.125f);
            float e1 = __expf(sacc[t][1] * 0.125f);
            float e2 = __expf(sacc[t][2] * 0.125f);
            float e3 = __expf(sacc[t][3] * 0.125f);
            rl += e0 + e1;
            rh += e2 + e3;
            pa[t >> 1][(t & 1) * 2]     = packbf2(e0, e1);
            pa[t >> 1][(t & 1) * 2 + 1] = packbf2(e2, e3);
        }

        #pragma unroll
        for (int ks = 0; ks < 4; ks++) {
            #pragma unroll
            for (int dp = 0; dp < 4; dp++) {
                int drow = dp * 16 + (lg >> 1) * 8 + lr;
                int jcol = ks * 16 + (lg & 1) * 8;
                unsigned int a = vb + drow * (KJ * 2) + jcol * 2;
                unsigned int b0, b1, b2, b3;
                LDSM4(b0, b1, b2, b3, a);
                MMA16816(oacc[dp * 2],     pa[ks], b0, b1);
                MMA16816(oacc[dp * 2 + 1], pa[ks], b2, b3);
            }
        }
    }

    rl += __shfl_xor_sync(~0u, rl, 1); rl += __shfl_xor_sync(~0u, rl, 2);
    rh += __shfl_xor_sync(~0u, rh, 1); rh += __shfl_xor_sync(~0u, rh, 2);
    float il = 1.f / rl, ih = 1.f / rh;

    __syncthreads();
    #pragma unroll
    for (int t = 0; t < 8; t++) {
        int dcol = t * 8 + qtid * 2;
        Qs[dcol * QI + ibase + gid]           = __float2bfloat16(oacc[t][0] * il);
        Qs[(dcol + 1) * QI + ibase + gid]     = __float2bfloat16(oacc[t][1] * il);
        Qs[dcol * QI + ibase + gid + 8]       = __float2bfloat16(oacc[t][2] * ih);
        Qs[(dcol + 1) * QI + ibase + gid + 8] = __float2bfloat16(oacc[t][3] * ih);
    }
    __syncthreads();

    {
        int d = tid >> 2, c = (tid & 3) * 32;
        const uint4* s = (const uint4*)&Qs[d * QI + c];
        uint4* t = (uint4*)&op[(size_t)d * LSP + i0 + c];
        t[0] = s[0]; t[1] = s[1]; t[2] = s[2]; t[3] = s[3];
    }
}

// ---------------- fused attention + proj (producer/consumer flags) ----------
// bids [0, 1024): attention (x=bid&7 l-tile, h=(bid>>3)&7, b=bid>>6);
// bids [1024, 1536): proj, spins until its 8 attn producers (same b, l-tile) done.
__global__ __launch_bounds__(256, 2) void attn_proj(const bf16* __restrict__ q,
                                                    const bf16* __restrict__ kv,
                                                    bf16* __restrict__ o,
                                                    const bf16* __restrict__ wp,
                                                    const float* __restrict__ pb,
                                                    const float* __restrict__ xres,
                                                    float* __restrict__ out)
{
    extern __shared__ char smraw[];
    int bid = blockIdx.x;
    if (bid < 1024) {
        int xt = bid & 7, h = (bid >> 3) & 7, b = bid >> 6;
        attn_body(q, kv, o, xt, h, b, smraw);
        __threadfence();
        __syncthreads();
        if (threadIdx.x == 0) atomicAdd(&g_flag[b * 8 + xt], 1u);
    } else {
        int pid = bid - 1024;
        int xt = pid & 7, y = (pid >> 3) & 3, b = pid >> 5;
        if (threadIdx.x == 0) {
            while (atomicAdd(&g_flag[b * 8 + xt], 0u) < 8u) __nanosleep(200);
        }
        __syncthreads();
        gemm_body<false>(o, wp, pb, xres, out, CCH, b, y * 128, xt * 128, smraw);
    }
}

// ---------------- launch ----------------
extern "C" void kernel_launch(void* const* d_in, const int* in_sizes, int n_in,
                              void* d_out, int out_size)
{
    const float* x   = (const float*)d_in[0];
    const float* ctx = (const float*)d_in[1];
    const float* nqw = (const float*)d_in[2];
    const float* nqb = (const float*)d_in[3];
    const float* nkw = (const float*)d_in[4];
    const float* nkb = (const float*)d_in[5];
    const float* cqw = (const float*)d_in[6];
    const float* cqb = (const float*)d_in[7];
    const float* ckw = (const float*)d_in[8];
    const float* ckb = (const float*)d_in[9];
    const float* pw  = (const float*)d_in[10];
    const float* pb  = (const float*)d_in[11];
    float* out = (float*)d_out;

    bf16 *xn, *cn, *q, *kv, *o, *wq, *wkv, *wp;
    cudaGetSymbolAddress((void**)&xn,  g_xn);
    cudaGetSymbolAddress((void**)&cn,  g_cn);
    cudaGetSymbolAddress((void**)&q,   g_q);
    cudaGetSymbolAddress((void**)&kv,  g_kv);
    cudaGetSymbolAddress((void**)&o,   g_o);
    cudaGetSymbolAddress((void**)&wq,  g_wq);
    cudaGetSymbolAddress((void**)&wkv, g_wkv);
    cudaGetSymbolAddress((void**)&wp,  g_wp);

    const int gsmem = 6 * A_ST;   // 98304 B (gemm needs; attn path uses 54272 of it)
    cudaFuncSetAttribute(gemm_qkv, cudaFuncAttributeMaxDynamicSharedMemorySize, gsmem);
    cudaFuncSetAttribute(attn_proj, cudaFuncAttributeMaxDynamicSharedMemorySize, gsmem);

    const int nq = CCH * CCH / 4, nkv = 2 * CCH * CCH / 4;
    const int cvt_blocks = (nq + nkv + nq + 255) / 256;   // 1024

    head_kernel<<<2 * BATCH * 32 + cvt_blocks, 256>>>(
        x, nqw, nqb, xn, ctx, nkw, nkb, cn,
        cqw, wq, nq, ckw, wkv, nkv, pw, wp, nq);

    gemm_qkv<<<dim3(8, 12, BATCH), 256, gsmem>>>(xn, cn, wq, wkv, cqb, ckb, q, kv);

    attn_proj<<<1024 + 512, 256, gsmem>>>(q, kv, o, wp, pb, x, out);
}